// round 17
// baseline (speedup 1.0000x reference)
#include <cuda_runtime.h>
#include <cuda_bf16.h>
#include <cstdint>
#include <cstddef>

// RNN_5188320494079: N=64, T=1024, D=256, H=256, fp32.
// Inputs: x[N,T,D], h0[N,H], Wx[D,H], Wh[H,H], b[H]. Output: [N,T,H].
//
// Kernel 1: Out = x @ Wx + b (packed-f32x2 SGEMM, in-place into d_out).
// Kernel 2: DUAL-BATCH pipelined cluster scan. 64 CTAs = 32 clusters(2);
//   each cluster owns TWO batch sequences (nA, nB) and alternates phases:
//   phase A computes batch A's step while batch B's fabric traffic flies,
//   and vice versa -> the ~450cyc DSMEM hop is fully hidden under the other
//   batch's compute. Wh slice (registers) is shared by both batches.
//   Per phase: R16 machinery (rank-adjusted rows, single-waiter mbar +
//   named barrier, 64 aggregated b64 st.async, LDS.128 reduce).

#define RNN_N 64
#define RNN_T 1024
#define RNN_D 256
#define RNN_H 256
#define HHALF 128

typedef unsigned long long ull;

__device__ __forceinline__ void ffma2(ull& d, ull a, ull b) {
    asm("fma.rn.f32x2 %0, %1, %2, %0;" : "+l"(d) : "l"(a), "l"(b));
}
__device__ __forceinline__ float2 u2f(ull u) {
    float2 f;
    asm("mov.b64 {%0, %1}, %2;" : "=f"(f.x), "=f"(f.y) : "l"(u));
    return f;
}
__device__ __forceinline__ ull f2u(float a, float b) {
    ull u;
    asm("mov.b64 %0, {%1, %2};" : "=l"(u) : "f"(a), "f"(b));
    return u;
}
__device__ __forceinline__ uint32_t smem_u32(const void* p) {
    uint32_t a;
    asm("{ .reg .u64 t; cvta.to.shared.u64 t, %1; cvt.u32.u64 %0, t; }"
        : "=r"(a) : "l"(p));
    return a;
}
__device__ __forceinline__ void mbar_wait(uint32_t addr, uint32_t parity) {
    asm volatile(
        "{\n\t.reg .pred P;\n\t"
        "WL%=:\n\t"
        "mbarrier.try_wait.parity.acquire.cta.shared::cta.b64 P, [%0], %1, 0x989680;\n\t"
        "@P bra.uni WD%=;\n\t"
        "bra.uni WL%=;\n\t"
        "WD%=:\n\t}"
        :: "r"(addr), "r"(parity) : "memory");
}
__device__ __forceinline__ void mbar_expect(uint32_t addr, uint32_t bytes) {
    asm volatile("mbarrier.arrive.expect_tx.shared::cta.b64 _, [%0], %1;"
                 :: "r"(addr), "r"(bytes) : "memory");
}

// ---------------------------------------------------------------------------
// Kernel 1: smem-tiled SGEMM, BM=128 BN=128 BK=16, 256 thr, f32x2 micro-kernel.
// (unchanged — FFMA2-bound, ~190us)
// ---------------------------------------------------------------------------
__global__ __launch_bounds__(256, 2)
void gemm_xw_kernel(const float* __restrict__ X, const float* __restrict__ Wx,
                    const float* __restrict__ bias, float* __restrict__ Out) {
    __shared__ __align__(16) float2 Asd[16][128];
    __shared__ __align__(16) float  Bs[16][128];

    const int tid = threadIdx.x;
    const int tx = tid & 15;
    const int ty = tid >> 4;
    const int m0 = blockIdx.x * 128;
    const int n0 = blockIdx.y * 128;

    const int a_row = tid >> 2;
    const int a_col = (tid & 3) << 2;
    const int b_row = tid >> 5;
    const int b_col = (tid & 31) << 2;

    ull acc[8][4];
#pragma unroll
    for (int i = 0; i < 8; i++)
#pragma unroll
        for (int j = 0; j < 4; j++) acc[i][j] = 0ull;

    const float* Xa0 = &X[(size_t)(m0 + a_row) * RNN_D + a_col];
    const float* Xa1 = &X[(size_t)(m0 + a_row + 64) * RNN_D + a_col];
    const float* Wb0 = &Wx[(size_t)b_row * RNN_H + n0 + b_col];
    const float* Wb1 = &Wx[(size_t)(b_row + 8) * RNN_H + n0 + b_col];

    for (int k0 = 0; k0 < RNN_D; k0 += 16) {
        float4 av0 = __ldcs(reinterpret_cast<const float4*>(Xa0 + k0));
        float4 av1 = __ldcs(reinterpret_cast<const float4*>(Xa1 + k0));
        float4 bv0 = *reinterpret_cast<const float4*>(Wb0 + (size_t)k0 * RNN_H);
        float4 bv1 = *reinterpret_cast<const float4*>(Wb1 + (size_t)k0 * RNN_H);
        __syncthreads();
        Asd[a_col + 0][a_row] = make_float2(av0.x, av0.x);
        Asd[a_col + 1][a_row] = make_float2(av0.y, av0.y);
        Asd[a_col + 2][a_row] = make_float2(av0.z, av0.z);
        Asd[a_col + 3][a_row] = make_float2(av0.w, av0.w);
        Asd[a_col + 0][a_row + 64] = make_float2(av1.x, av1.x);
        Asd[a_col + 1][a_row + 64] = make_float2(av1.y, av1.y);
        Asd[a_col + 2][a_row + 64] = make_float2(av1.z, av1.z);
        Asd[a_col + 3][a_row + 64] = make_float2(av1.w, av1.w);
        *reinterpret_cast<float4*>(&Bs[b_row][b_col]) = bv0;
        *reinterpret_cast<float4*>(&Bs[b_row + 8][b_col]) = bv1;
        __syncthreads();
#pragma unroll
        for (int k = 0; k < 16; k++) {
            const ulonglong2* ad = reinterpret_cast<const ulonglong2*>(&Asd[k][ty * 8]);
            ulonglong2 aa0 = ad[0], aa1 = ad[1], aa2 = ad[2], aa3 = ad[3];
            const ulonglong2* bd = reinterpret_cast<const ulonglong2*>(&Bs[k][tx * 8]);
            ulonglong2 bb0 = bd[0], bb1 = bd[1];
            ull ap[8] = {aa0.x, aa0.y, aa1.x, aa1.y, aa2.x, aa2.y, aa3.x, aa3.y};
            ull bp[4] = {bb0.x, bb0.y, bb1.x, bb1.y};
#pragma unroll
            for (int i = 0; i < 8; i++) {
                ffma2(acc[i][0], ap[i], bp[0]);
                ffma2(acc[i][1], ap[i], bp[1]);
                ffma2(acc[i][2], ap[i], bp[2]);
                ffma2(acc[i][3], ap[i], bp[3]);
            }
        }
    }

    float4 bb0 = *reinterpret_cast<const float4*>(&bias[n0 + tx * 8]);
    float4 bb1 = *reinterpret_cast<const float4*>(&bias[n0 + tx * 8 + 4]);
    float bb[8] = {bb0.x, bb0.y, bb0.z, bb0.w, bb1.x, bb1.y, bb1.z, bb1.w};
#pragma unroll
    for (int i = 0; i < 8; i++) {
        size_t r = (size_t)(m0 + ty * 8 + i) * RNN_H + n0 + tx * 8;
        float2 v0 = u2f(acc[i][0]), v1 = u2f(acc[i][1]);
        float2 v2 = u2f(acc[i][2]), v3 = u2f(acc[i][3]);
        float4 o0 = make_float4(v0.x + bb[0], v0.y + bb[1], v1.x + bb[2], v1.y + bb[3]);
        float4 o1 = make_float4(v2.x + bb[4], v2.y + bb[5], v3.x + bb[6], v3.y + bb[7]);
        *reinterpret_cast<float4*>(&Out[r]) = o0;
        *reinterpret_cast<float4*>(&Out[r + 4]) = o1;
    }
}

// ---------------------------------------------------------------------------
// Kernel 2: dual-batch pipelined cluster scan.
// Grid 64 CTAs = 32 clusters(2). Cluster cl = blockIdx>>1 handles batches
// nA = 2*cl, nB = 2*cl+1; rank owns output cols [rank*128,+128) of both.
// 512 thr: col = tid&127, q = tid>>7; ibase = ((q+2*rank)&3)*64 so q=0,1 are
// always OWN h rows. Wh slice: 32 packed reg pairs, SHARED by both batches.
// SMEM layout (B offsets derived from A by constants):
//   hbuf[batch][buf][256]  (batch stride 2048B)
//   Ps[batch][128][4]      (separate per batch: closes cross-phase WAR)
//   mbars[batch][parity]   (batch stride 16B)
// Phase X at step t: single-waiter (tid256) waits BX[t&1] par ((t-1)>>1)&1,
// re-arms, bar.sync 1 releases warps 8-15; all compute 32 FFMA2 -> PsX;
// __syncthreads; finalize (tid<128) LDS.128 reduce + tanh + 64 aggregated
// b64 st.async -> peer hbufX[nxt] + BX[(t+1)&1] + local store + __stcs out.
// A's fabric flight is covered by phase B and vice versa.
// ---------------------------------------------------------------------------
__global__ __launch_bounds__(512, 1) __cluster_dims__(2, 1, 1)
void rnn_scan_kernel(const float* __restrict__ h0,
                     const float* __restrict__ Wh,
                     float* Out) {
    __shared__ __align__(16) float hbuf[2][2][RNN_H];     // [batch][buf], 4KB
    __shared__ __align__(16) float Ps[2][HHALF][4];       // [batch], 4KB
    __shared__ __align__(16) unsigned long long mbars[2][2]; // [batch][parity]

    const int tid = threadIdx.x;
    uint32_t rank;
    asm("mov.u32 %0, %%cluster_ctarank;" : "=r"(rank));
    const uint32_t peer = rank ^ 1u;
    const int cl = blockIdx.x >> 1;          // cluster index = batch pair
    const int nA = cl * 2;                   // batch A (B = nA+1)
    const int col = tid & 127;
    const int q = tid >> 7;                  // 0..3
    const int ibase = ((q + 2 * (int)rank) & 3) * 64;   // q=0,1 -> own rows
    const bool needs_peer = (q >= 2);
    const int gcol = (int)rank * HHALF + col;

    // byte offsets of batch-B structures relative to batch-A
    const uint32_t HB_OFF = (uint32_t)((char*)&hbuf[1][0][0] - (char*)&hbuf[0][0][0]);
    const uint32_t MB_OFF = (uint32_t)((char*)&mbars[1][0] - (char*)&mbars[0][0]);

    const uint32_t mbA0 = smem_u32((const void*)&mbars[0][0]);
    const uint32_t mbA1 = smem_u32((const void*)&mbars[0][1]);

    if (tid == 0) {
#pragma unroll
        for (int b = 0; b < 2; b++)
#pragma unroll
            for (int p = 0; p < 2; p++)
                asm volatile("mbarrier.init.shared.b64 [%0], %1;"
                             :: "r"(smem_u32((const void*)&mbars[b][p])), "r"(1)
                             : "memory");
    }

    // Register Wh slice: rows ibase..ibase+63 x col gcol, 32 packed row-pairs.
    ull wq[32];
#pragma unroll
    for (int k = 0; k < 32; k++) {
        int r = ibase + 2 * k;
        wq[k] = f2u(__ldg(&Wh[(size_t)r * RNN_H + gcol]),
                    __ldg(&Wh[(size_t)(r + 1) * RNN_H + gcol]));
    }

    float* outA = Out + (size_t)nA * RNN_T * RNN_H;
    const size_t OUTB = (size_t)RNN_T * RNN_H;   // batch B output offset

    if (tid < RNN_H) {
        hbuf[0][0][tid] = h0[(size_t)nA * RNN_H + tid];
        hbuf[1][0][tid] = h0[(size_t)(nA + 1) * RNN_H + tid];
    }

    // finalize-lane state (A-side addresses; B derived by +HB_OFF/+MB_OFF)
    float xwA = 0.f, xwB = 0.f;
    uint32_t rH0 = 0, rH1 = 0, rmB0 = 0, rmB1 = 0;
    if (tid < HHALF) {
        xwA = __ldcg(&outA[gcol]);
        xwB = __ldcg(&outA[OUTB + gcol]);
        if ((tid & 1) == 0) {
            uint32_t l0 = smem_u32(&hbuf[0][0][gcol]);   // 8B-aligned
            uint32_t l1 = smem_u32(&hbuf[0][1][gcol]);
            asm("mapa.shared::cluster.u32 %0, %1, %2;" : "=r"(rH0) : "r"(l0), "r"(peer));
            asm("mapa.shared::cluster.u32 %0, %1, %2;" : "=r"(rH1) : "r"(l1), "r"(peer));
            asm("mapa.shared::cluster.u32 %0, %1, %2;" : "=r"(rmB0) : "r"(mbA0), "r"(peer));
            asm("mapa.shared::cluster.u32 %0, %1, %2;" : "=r"(rmB1) : "r"(mbA1), "r"(peer));
        }
    }
    __syncthreads();
    if (tid == 0) {   // arm both parities for both batches (consumed t=1, t=2)
        mbar_expect(mbA1, 512u);
        mbar_expect(mbA0, 512u);
        mbar_expect(mbA1 + MB_OFF, 512u);
        mbar_expect(mbA0 + MB_OFF, 512u);
    }
    asm volatile("barrier.cluster.arrive.aligned;" ::: "memory");
    asm volatile("barrier.cluster.wait.aligned;" ::: "memory");

    int cur = 0;
    for (int t = 0; t < RNN_T; t++) {
        const int nxt = cur ^ 1;
        const uint32_t wpar = (uint32_t)((t - 1) >> 1) & 1u;
        const uint32_t bsel = (uint32_t)(t & 1);
        const uint32_t ssel = (uint32_t)((t + 1) & 1);

#pragma unroll
        for (int ph = 0; ph < 2; ph++) {     // ph 0 = batch A, ph 1 = batch B
            const uint32_t hoff = ph ? HB_OFF : 0u;
            const uint32_t moff = ph ? MB_OFF : 0u;

            // peer-row warps: single-lane mbar wait + named-barrier release
            if (needs_peer && t > 0) {
                if (tid == 256) {
                    uint32_t bw = (bsel ? mbA1 : mbA0) + moff;
                    mbar_wait(bw, wpar);
                    if (t + 2 < RNN_T) mbar_expect(bw, 512u);   // re-arm t+2
                }
                asm volatile("bar.sync 1, 256;" ::: "memory");  // warps 8-15
            }

            // 32 packed FFMA2 over my 64 rows of this batch's h
            const ulonglong2* hp = reinterpret_cast<const ulonglong2*>(
                &hbuf[ph][cur][ibase]);
            ull a0 = 0ull, a1 = 0ull;
#pragma unroll
            for (int m = 0; m < 16; m++) {
                ulonglong2 hv = hp[m];
                ffma2(a0, hv.x, wq[2 * m]);
                ffma2(a1, hv.y, wq[2 * m + 1]);
            }
            float2 f0 = u2f(a0), f1 = u2f(a1);
            Ps[ph][col][q] = (f0.x + f0.y) + (f1.x + f1.y);
            __syncthreads();

            if (tid < HHALF) {
                float4 v = *reinterpret_cast<const float4*>(&Ps[ph][col][0]);
                float xw = ph ? xwB : xwA;
                float z = xw + ((v.x + v.y) + (v.z + v.w));
                float e = __expf(2.0f * z);                  // tanh via MUFU
                float hn = 1.0f - __fdividef(2.0f, e + 1.0f);
                if (t + 1 < RNN_T) {
                    float hr = __shfl_down_sync(0xffffffffu, hn, 1);
                    if ((tid & 1) == 0) {                    // 64 sends, 512B
                        ull pkt = f2u(hn, hr);
                        uint32_t ra = (nxt ? rH1 : rH0) + hoff;
                        uint32_t rb = (ssel ? rmB1 : rmB0) + moff;
                        asm volatile(
                            "st.async.shared::cluster.mbarrier::complete_tx::bytes.b64 [%0], %1, [%2];"
                            :: "r"(ra), "l"(pkt), "r"(rb) : "memory");
                    }
                    hbuf[ph][nxt][gcol] = hn;                // local copy
                }
                float* op = outA + (ph ? OUTB : 0) + (size_t)t * RNN_H + gcol;
                __stcs(op, hn);                              // overwrite xW slot
                float xwn = 0.f;
                if (t + 1 < RNN_T)
                    xwn = __ldcg(outA + (ph ? OUTB : 0) +
                                 (size_t)(t + 1) * RNN_H + gcol);
                if (ph) xwB = xwn; else xwA = xwn;
            }
            // no trailing sync: the NEXT phase's __syncthreads orders
            // finalize stores/reads against the other batch's compute;
            // Ps is per-batch so no WAR across phases.
        }
        cur ^= 1;
    }

    // keep SMEM alive until all remote traffic has drained cluster-wide
    asm volatile("barrier.cluster.arrive.aligned;" ::: "memory");
    asm volatile("barrier.cluster.wait.aligned;" ::: "memory");
}

// ---------------------------------------------------------------------------
extern "C" void kernel_launch(void* const* d_in, const int* in_sizes, int n_in,
                              void* d_out, int out_size) {
    const float* x  = (const float*)d_in[0];   // [N,T,D]
    const float* h0 = (const float*)d_in[1];   // [N,H]
    const float* Wx = (const float*)d_in[2];   // [D,H]
    const float* Wh = (const float*)d_in[3];   // [H,H]
    const float* b  = (const float*)d_in[4];   // [H]
    float* out = (float*)d_out;                // [N,T,H]

    (void)in_sizes; (void)n_in; (void)out_size;

    dim3 g1((RNN_N * RNN_T) / 128, RNN_H / 128);
    gemm_xw_kernel<<<g1, 256>>>(x, Wx, b, out);

    // 64 CTAs = 32 clusters(2), two batches per cluster
    rnn_scan_kernel<<<RNN_N, 512>>>(h0, Wh, out);
}